// round 1
// baseline (speedup 1.0000x reference)
#include <cuda_runtime.h>

// Block k-offsets into the 100-wide feature vector, block order b = 4*i1 + i2,
// AM = [0,0,1,2], size(b) = (2*l1+1)*(2*l2+1).
__constant__ int c_prefix[16] = {0,1,2,5,10,11,12,15,20,23,26,35,50,55,60,75};

struct CgPtrs { const float* p[9]; };

// Decompose dense row/col index r of atom type T into:
//   iam = COMMON_AM slot index (0..3), l = angular momentum, loc = index within 2l+1
// type 0 (dim 4):  slot0 l=0 @0, slot2 l=1 @1   (slots 1,3 unused)
// type 1 (dim 10): slot0 l=0 @0, slot1 l=0 @1, slot2 l=1 @2, slot3 l=2 @5
__device__ __forceinline__ void decomp(int T, int r, int& iam, int& l, int& loc) {
    if (T == 0) {
        if (r == 0) { iam = 0; l = 0; loc = 0; }
        else        { iam = 2; l = 1; loc = r - 1; }
    } else {
        if (r == 0)      { iam = 0; l = 0; loc = 0; }
        else if (r == 1) { iam = 1; l = 0; loc = 0; }
        else if (r < 5)  { iam = 2; l = 1; loc = r - 2; }
        else             { iam = 3; l = 2; loc = r - 5; }
    }
}

// dot( feature_edge[e][koff : koff+size] (+ feature_node[n1] on self edges), cg_row )
__device__ __forceinline__ float edge_dot(
    const float* __restrict__ fe, const float* __restrict__ fn,
    const float* __restrict__ S,
    const int* __restrict__ n1a, const int* __restrict__ n2a,
    int e, int koff, const float* __restrict__ cg, int size)
{
    int a = __ldg(n1a + e);
    int b = __ldg(n2a + e);
    const float* row = fe + (long long)e * 100 + koff;
    bool self = false;
    if (a == b) {
        float sx = __ldg(S + 3 * e), sy = __ldg(S + 3 * e + 1), sz = __ldg(S + 3 * e + 2);
        self = (sx * sx + sy * sy + sz * sz) < 1e-12f;
    }
    float acc = 0.f;
    if (self) {
        const float* nrow = fn + (long long)a * 100 + koff;
        #pragma unroll 5
        for (int k = 0; k < size; k++)
            acc += (__ldg(row + k) + __ldg(nrow + k)) * __ldg(cg + k);
    } else {
        #pragma unroll 5
        for (int k = 0; k < size; k++)
            acc += __ldg(row + k) * __ldg(cg + k);
    }
    return acc;
}

// One thread per (local edge, output element). out[i][r][c] = 0.5*(pre[e][r][c] + pre[inv(e)][c][r])
template<int T1, int T2>
__global__ void ham_kernel(
    const float* __restrict__ fe, const float* __restrict__ fn,
    const float* __restrict__ S,
    const int* __restrict__ n1a, const int* __restrict__ n2a,
    const int* __restrict__ einv,
    const int* __restrict__ sel, int n_sel,
    CgPtrs cg, float* __restrict__ out)
{
    constexpr int D1 = T1 ? 10 : 4;
    constexpr int D2 = T2 ? 10 : 4;
    constexpr int ELEMS = D1 * D2;
    long long total = (long long)n_sel * ELEMS;
    for (long long t = blockIdx.x * (long long)blockDim.x + threadIdx.x; t < total;
         t += (long long)gridDim.x * blockDim.x) {
        int elem = (int)(t % ELEMS);
        int i    = (int)(t / ELEMS);
        int e = __ldg(sel + i);
        int r = elem / D2;
        int c = elem % D2;

        int i1, l1, li, i2, l2, lj;
        decomp(T1, r, i1, l1, li);
        decomp(T2, c, i2, l2, lj);
        int w1 = 2 * l1 + 1, w2 = 2 * l2 + 1;
        int size = w1 * w2;

        // A = pre[e][r][c]  : block b = 4*i1+i2, cg_{l1,l2} row (li, lj)
        const float* cgA = cg.p[l1 * 3 + l2] + (li * w2 + lj) * size;
        float A = edge_dot(fe, fn, S, n1a, n2a, e, c_prefix[4 * i1 + i2], cgA, size);

        // B = pre[inv(e)][c][r] : pair (T2,T1), block 4*i2+i1, cg_{l2,l1} row (lj, li)
        int ie = __ldg(einv + e);
        const float* cgB = cg.p[l2 * 3 + l1] + (lj * w1 + li) * size;
        float B = edge_dot(fe, fn, S, n1a, n2a, ie, c_prefix[4 * i2 + i1], cgB, size);

        out[t] = 0.5f * (A + B);
    }
}

// g2b[sel_p[i]] = i  (written as float into the output tail)
__global__ void g2b_kernel(const int* __restrict__ s00, int n00,
                           const int* __restrict__ s01, int n01,
                           const int* __restrict__ s10, int n10,
                           const int* __restrict__ s11, int n11,
                           float* __restrict__ outg)
{
    int total = n00 + n01 + n10 + n11;
    for (int t = blockIdx.x * blockDim.x + threadIdx.x; t < total;
         t += gridDim.x * blockDim.x) {
        const int* s;
        int loc;
        if (t < n00)                   { s = s00; loc = t; }
        else if (t < n00 + n01)        { s = s01; loc = t - n00; }
        else if (t < n00 + n01 + n10)  { s = s10; loc = t - n00 - n01; }
        else                           { s = s11; loc = t - n00 - n01 - n10; }
        outg[__ldg(s + loc)] = (float)loc;
    }
}

extern "C" void kernel_launch(void* const* d_in, const int* in_sizes, int n_in,
                              void* d_out, int out_size) {
    const float* fn  = (const float*)d_in[0];   // feature_node  (N,100)
    const float* fe  = (const float*)d_in[1];   // feature_edge  (E,100)
    const float* S   = (const float*)d_in[2];   // S_hop         (E,3)
    const int*  eidx = (const int*)d_in[3];     // edge_index_hop (2,E) int32
    const int*  einv = (const int*)d_in[5];     // edge_inverse  (E,) int32
    CgPtrs cg;
    for (int i = 0; i < 9; i++) cg.p[i] = (const float*)d_in[6 + i];
    const int* s00 = (const int*)d_in[15]; int n00 = in_sizes[15];
    const int* s01 = (const int*)d_in[16]; int n01 = in_sizes[16];
    const int* s10 = (const int*)d_in[17]; int n10 = in_sizes[17];
    const int* s11 = (const int*)d_in[18]; int n11 = in_sizes[18];

    int E = in_sizes[1] / 100;
    const int* n1a = eidx;
    const int* n2a = eidx + E;
    float* out = (float*)d_out;

    long long o01 = 16LL * n00;
    long long o10 = o01 + 40LL * n01;
    long long o11 = o10 + 40LL * n10;
    long long og  = o11 + 100LL * n11;

    auto nblocks = [](long long tot) { return (unsigned)((tot + 255) / 256); };

    if (n00) ham_kernel<0,0><<<nblocks(16LL  * n00), 256>>>(fe, fn, S, n1a, n2a, einv, s00, n00, cg, out);
    if (n01) ham_kernel<0,1><<<nblocks(40LL  * n01), 256>>>(fe, fn, S, n1a, n2a, einv, s01, n01, cg, out + o01);
    if (n10) ham_kernel<1,0><<<nblocks(40LL  * n10), 256>>>(fe, fn, S, n1a, n2a, einv, s10, n10, cg, out + o10);
    if (n11) ham_kernel<1,1><<<nblocks(100LL * n11), 256>>>(fe, fn, S, n1a, n2a, einv, s11, n11, cg, out + o11);

    int tot = n00 + n01 + n10 + n11;
    if (tot) g2b_kernel<<<(tot + 255) / 256, 256>>>(s00, n00, s01, n01, s10, n10, s11, n11, out + og);

    (void)n_in; (void)out_size;
}

// round 2
// speedup vs baseline: 1.5872x; 1.5872x over previous
#include <cuda_runtime.h>

// Block k-offsets into the 100-wide feature vector, block order b = 4*i1 + i2.
__constant__ int c_prefix[16] = {0,1,2,5,10,11,12,15,20,23,26,35,50,55,60,75};
// Flattened CG storage: offsets/lengths for cg_{l1,l2}, p = l1*3+l2, len = s^2.
__constant__ int c_cgoff[9] = {0,1,10,35,44,125,350,375,600};
__constant__ int c_cglen[9] = {1,9,25,9,81,225,25,225,625};
#define CG_TOTAL 1225

struct CgPtrs { const float* p[9]; };

// Local index of each edge within its type-pair sel list.
__device__ int g2b_scratch[524288];

// Decompose dense row/col index r of atom type T into (slot, l, loc).
__device__ __forceinline__ void decomp(int T, int r, int& iam, int& l, int& loc) {
    if (T == 0) {
        if (r == 0) { iam = 0; l = 0; loc = 0; }
        else        { iam = 2; l = 1; loc = r - 1; }
    } else {
        if (r == 0)      { iam = 0; l = 0; loc = 0; }
        else if (r == 1) { iam = 1; l = 0; loc = 0; }
        else if (r < 5)  { iam = 2; l = 1; loc = r - 2; }
        else             { iam = 3; l = 2; loc = r - 5; }
    }
}

// Pass 1: g2b scatter (int scratch for partner lookup + float output tail).
__global__ void g2b_kernel(const int* __restrict__ s00, int n00,
                           const int* __restrict__ s01, int n01,
                           const int* __restrict__ s10, int n10,
                           const int* __restrict__ s11, int n11,
                           float* __restrict__ outg)
{
    int total = n00 + n01 + n10 + n11;
    for (int t = blockIdx.x * blockDim.x + threadIdx.x; t < total;
         t += gridDim.x * blockDim.x) {
        const int* s; int loc;
        if (t < n00)                  { s = s00; loc = t; }
        else if (t < n00 + n01)       { s = s01; loc = t - n00; }
        else if (t < n00 + n01 + n10) { s = s10; loc = t - n00 - n01; }
        else                          { s = s11; loc = t - n00 - n01 - n10; }
        int e = __ldg(s + loc);
        g2b_scratch[e] = loc;
        outg[e] = (float)loc;
    }
}

__device__ __forceinline__ void load_cg_shared(float* s_cg, const CgPtrs& cg) {
    for (int t = threadIdx.x; t < CG_TOTAL; t += blockDim.x) {
        int p = 0;
        #pragma unroll
        for (int q = 1; q < 9; q++) if (t >= c_cgoff[q]) p = q;
        s_cg[t] = __ldg(cg.p[p] + (t - c_cgoff[p]));
    }
}

// Load one fe row (with self-edge node-feature addition) into shared (warp-coop).
__device__ __forceinline__ void load_row(
    float* dst, const float* __restrict__ fe, const float* __restrict__ fn,
    const float* __restrict__ S, const int* __restrict__ n1a,
    const int* __restrict__ n2a, int e, int lane)
{
    int a = __ldg(n1a + e);
    int b = __ldg(n2a + e);
    bool self = false;
    if (a == b) {
        float sx = __ldg(S + 3 * e), sy = __ldg(S + 3 * e + 1), sz = __ldg(S + 3 * e + 2);
        self = (sx * sx + sy * sy + sz * sz) < 1e-12f;
    }
    const float* row = fe + (long long)e * 100;
    if (self) {
        const float* nrow = fn + (long long)a * 100;
        for (int t = lane; t < 100; t += 32) dst[t] = __ldg(row + t) + __ldg(nrow + t);
    } else {
        for (int t = lane; t < 100; t += 32) dst[t] = __ldg(row + t);
    }
}

// Same-type pairs (T,T): warp per local edge j; pair-dedup via partner index p.
template<int T>
__global__ void ham_same(
    const float* __restrict__ fe, const float* __restrict__ fn,
    const float* __restrict__ S,
    const int* __restrict__ n1a, const int* __restrict__ n2a,
    const int* __restrict__ einv,
    const int* __restrict__ sel, int n_sel,
    CgPtrs cg, float* __restrict__ out)
{
    constexpr int D = T ? 10 : 4;
    constexpr int ELEMS = D * D;
    __shared__ float s_cg[CG_TOTAL];
    __shared__ float s_fe[8][2][100];
    load_cg_shared(s_cg, cg);
    __syncthreads();

    int warp = threadIdx.x >> 5;
    int lane = threadIdx.x & 31;
    int j = blockIdx.x * 8 + warp;
    if (j >= n_sel) return;

    int e  = __ldg(sel + j);
    int ie = __ldg(einv + e);
    int p  = g2b_scratch[ie];
    if (p < j) return;                 // partner warp owns this pair (warp-uniform)
    bool selfpair = (p == j);          // ie == e

    float* shA = s_fe[warp][0];
    float* shB = selfpair ? shA : s_fe[warp][1];
    load_row(shA, fe, fn, S, n1a, n2a, e, lane);
    if (!selfpair) load_row(shB, fe, fn, S, n1a, n2a, ie, lane);
    __syncwarp();

    for (int el = lane; el < ELEMS; el += 32) {
        int r = el / D, c = el % D;
        int i1, l1, li, i2, l2, lj;
        decomp(T, r, i1, l1, li);
        decomp(T, c, i2, l2, lj);
        int w1 = 2 * l1 + 1, w2 = 2 * l2 + 1, sz = w1 * w2;
        const float* cgA = s_cg + c_cgoff[l1 * 3 + l2] + (li * w2 + lj) * sz;
        const float* cgB = s_cg + c_cgoff[l2 * 3 + l1] + (lj * w1 + li) * sz;
        const float* fA = shA + c_prefix[4 * i1 + i2];
        const float* fB = shB + c_prefix[4 * i2 + i1];
        float A = 0.f, B = 0.f;
        #pragma unroll 5
        for (int k = 0; k < sz; k++) { A += fA[k] * cgA[k]; B += fB[k] * cgB[k]; }
        float M = 0.5f * (A + B);
        out[(long long)j * ELEMS + el] = M;
        if (!selfpair) out[(long long)p * ELEMS + c * D + r] = M;
    }
}

// Cross pairs: warp per j in sel01; writes ham01[j] and ham10[p] = transpose.
__global__ void ham_cross(
    const float* __restrict__ fe, const float* __restrict__ fn,
    const float* __restrict__ S,
    const int* __restrict__ n1a, const int* __restrict__ n2a,
    const int* __restrict__ einv,
    const int* __restrict__ sel01, int n01,
    CgPtrs cg, float* __restrict__ out01, float* __restrict__ out10)
{
    constexpr int D1 = 4, D2 = 10, ELEMS = 40;
    __shared__ float s_cg[CG_TOTAL];
    __shared__ float s_fe[8][2][100];
    load_cg_shared(s_cg, cg);
    __syncthreads();

    int warp = threadIdx.x >> 5;
    int lane = threadIdx.x & 31;
    int j = blockIdx.x * 8 + warp;
    if (j >= n01) return;

    int e  = __ldg(sel01 + j);
    int ie = __ldg(einv + e);
    int p  = g2b_scratch[ie];          // index within sel10

    float* shA = s_fe[warp][0];
    float* shB = s_fe[warp][1];
    load_row(shA, fe, fn, S, n1a, n2a, e, lane);
    load_row(shB, fe, fn, S, n1a, n2a, ie, lane);
    __syncwarp();

    for (int el = lane; el < ELEMS; el += 32) {
        int r = el / D2, c = el % D2;
        int i1, l1, li, i2, l2, lj;
        decomp(0, r, i1, l1, li);
        decomp(1, c, i2, l2, lj);
        int w1 = 2 * l1 + 1, w2 = 2 * l2 + 1, sz = w1 * w2;
        const float* cgA = s_cg + c_cgoff[l1 * 3 + l2] + (li * w2 + lj) * sz;
        const float* cgB = s_cg + c_cgoff[l2 * 3 + l1] + (lj * w1 + li) * sz;
        const float* fA = shA + c_prefix[4 * i1 + i2];
        const float* fB = shB + c_prefix[4 * i2 + i1];
        float A = 0.f, B = 0.f;
        #pragma unroll 5
        for (int k = 0; k < sz; k++) { A += fA[k] * cgA[k]; B += fB[k] * cgB[k]; }
        float M = 0.5f * (A + B);
        out01[(long long)j * ELEMS + r * D2 + c] = M;
        out10[(long long)p * ELEMS + c * D1 + r] = M;
    }
}

extern "C" void kernel_launch(void* const* d_in, const int* in_sizes, int n_in,
                              void* d_out, int out_size) {
    const float* fn  = (const float*)d_in[0];   // feature_node  (N,100)
    const float* fe  = (const float*)d_in[1];   // feature_edge  (E,100)
    const float* S   = (const float*)d_in[2];   // S_hop         (E,3)
    const int*  eidx = (const int*)d_in[3];     // edge_index_hop (2,E)
    const int*  einv = (const int*)d_in[5];     // edge_inverse  (E,)
    CgPtrs cg;
    for (int i = 0; i < 9; i++) cg.p[i] = (const float*)d_in[6 + i];
    const int* s00 = (const int*)d_in[15]; int n00 = in_sizes[15];
    const int* s01 = (const int*)d_in[16]; int n01 = in_sizes[16];
    const int* s10 = (const int*)d_in[17]; int n10 = in_sizes[17];
    const int* s11 = (const int*)d_in[18]; int n11 = in_sizes[18];

    int E = in_sizes[1] / 100;
    const int* n1a = eidx;
    const int* n2a = eidx + E;
    float* out = (float*)d_out;

    long long o01 = 16LL * n00;
    long long o10 = o01 + 40LL * n01;
    long long o11 = o10 + 40LL * n10;
    long long og  = o11 + 100LL * n11;

    int tot = n00 + n01 + n10 + n11;
    if (tot) g2b_kernel<<<(tot + 255) / 256, 256>>>(s00, n00, s01, n01, s10, n10, s11, n11, out + og);

    if (n00) ham_same<0><<<(n00 + 7) / 8, 256>>>(fe, fn, S, n1a, n2a, einv, s00, n00, cg, out);
    if (n01) ham_cross <<<(n01 + 7) / 8, 256>>>(fe, fn, S, n1a, n2a, einv, s01, n01, cg, out + o01, out + o10);
    if (n11) ham_same<1><<<(n11 + 7) / 8, 256>>>(fe, fn, S, n1a, n2a, einv, s11, n11, cg, out + o11);

    (void)n_in; (void)out_size; (void)s10; (void)n10;
}

// round 3
// speedup vs baseline: 1.7569x; 1.1069x over previous
#include <cuda_runtime.h>

#define CG_TOTAL 1225
struct CgPtrs { const float* p[9]; };

// Local index of each edge within its type-pair sel list.
__device__ int g2b_scratch[524288];

// Runtime tables for the cg staging loop.
__constant__ int c_cgoff[9] = {0,1,10,35,44,125,350,375,600};

// Compile-time tables.
__host__ __device__ constexpr int PFX(int b) {
    const int t[16] = {0,1,2,5,10,11,12,15,20,23,26,35,50,55,60,75};
    return t[b];
}
__host__ __device__ constexpr int CGO(int p) {
    const int t[9] = {0,1,10,35,44,125,350,375,600};
    return t[p];
}

// Pass 1: g2b scatter (int scratch for partner lookup + float output tail).
__global__ void g2b_kernel(const int* __restrict__ s00, int n00,
                           const int* __restrict__ s01, int n01,
                           const int* __restrict__ s10, int n10,
                           const int* __restrict__ s11, int n11,
                           float* __restrict__ outg)
{
    int total = n00 + n01 + n10 + n11;
    for (int t = blockIdx.x * blockDim.x + threadIdx.x; t < total;
         t += gridDim.x * blockDim.x) {
        const int* s; int loc;
        if (t < n00)                  { s = s00; loc = t; }
        else if (t < n00 + n01)       { s = s01; loc = t - n00; }
        else if (t < n00 + n01 + n10) { s = s10; loc = t - n00 - n01; }
        else                          { s = s11; loc = t - n00 - n01 - n10; }
        int e = __ldg(s + loc);
        g2b_scratch[e] = loc;
        outg[e] = (float)loc;
    }
}

__device__ __forceinline__ void load_cg_shared(float* s_cg, const CgPtrs& cg) {
    for (int t = threadIdx.x; t < CG_TOTAL; t += blockDim.x) {
        int p = 0;
        #pragma unroll
        for (int q = 1; q < 9; q++) if (t >= c_cgoff[q]) p = q;
        s_cg[t] = __ldg(cg.p[p] + (t - c_cgoff[p]));
    }
}

// Load one fe row (with self-edge node-feature addition) into shared (warp-coop).
__device__ __forceinline__ void load_row(
    float* dst, const float* __restrict__ fe, const float* __restrict__ fn,
    const float* __restrict__ S, const int* __restrict__ n1a,
    const int* __restrict__ n2a, int e, int lane)
{
    int a = __ldg(n1a + e);
    int b = __ldg(n2a + e);
    bool self = false;
    if (a == b) {
        float sx = __ldg(S + 3 * e), sy = __ldg(S + 3 * e + 1), sz = __ldg(S + 3 * e + 2);
        self = (sx * sx + sy * sy + sz * sz) < 1e-12f;
    }
    const float* row = fe + (long long)e * 100;
    if (self) {
        const float* nrow = fn + (long long)a * 100;
        for (int t = lane; t < 100; t += 32) dst[t] = __ldg(row + t) + __ldg(nrow + t);
    } else {
        for (int t = lane; t < 100; t += 32) dst[t] = __ldg(row + t);
    }
}

// One (slot1, slot2) block: compile-time geometry, conflict-free LDS,
// fully unrolled dot products. Lane l = li*W2+lj computes element (li,lj).
//   A = pre[e]  block (AM1,AM2) element (li,lj)
//   B = pre[ie] block (AM2,AM1) element (lj,li)
//   M = 0.5(A+B) -> o[(ROFF+li)*D2 + COFF+lj]; transpose -> oT.
template<int L1,int L2,int AM1,int AM2,int ROFF,int COFF,int D1,int D2>
__device__ __forceinline__ void do_block(
    int lane, const float* __restrict__ s_cg,
    const float* __restrict__ shA, const float* __restrict__ shB,
    float* __restrict__ o, float* __restrict__ oT)
{
    constexpr int W1 = 2*L1+1, W2 = 2*L2+1, SZ = W1*W2;
    if (lane < SZ) {
        int li = lane / W2, lj = lane % W2;
        const float* fA  = shA + PFX(4*AM1+AM2);
        const float* fB  = shB + PFX(4*AM2+AM1);
        const float* cgA = s_cg + CGO(L1*3+L2) + lane * SZ;
        const float* cgB = s_cg + CGO(L2*3+L1) + (lj*W1+li) * SZ;
        float A = 0.f, B = 0.f;
        #pragma unroll
        for (int k = 0; k < SZ; k++) { A += fA[k]*cgA[k]; B += fB[k]*cgB[k]; }
        float M = 0.5f * (A + B);
        o[(ROFF+li)*D2 + (COFF+lj)] = M;
        if (oT) oT[(COFF+lj)*D1 + (ROFF+li)] = M;
    }
}

// Same-type pairs (T,T): warp per local edge j; pair-dedup via partner index p.
template<int T>
__global__ void ham_same(
    const float* __restrict__ fe, const float* __restrict__ fn,
    const float* __restrict__ S,
    const int* __restrict__ n1a, const int* __restrict__ n2a,
    const int* __restrict__ einv,
    const int* __restrict__ sel, int n_sel,
    CgPtrs cg, float* __restrict__ out)
{
    constexpr int D = T ? 10 : 4;
    __shared__ float s_cg[CG_TOTAL];
    __shared__ float s_fe[8][2][100];
    load_cg_shared(s_cg, cg);
    __syncthreads();

    int warp = threadIdx.x >> 5;
    int lane = threadIdx.x & 31;
    int j = blockIdx.x * 8 + warp;
    if (j >= n_sel) return;

    int e  = __ldg(sel + j);
    int ie = __ldg(einv + e);
    int p  = g2b_scratch[ie];
    if (p < j) return;                 // partner warp owns this pair (warp-uniform)
    bool selfpair = (p == j);          // ie == e

    float* shA = s_fe[warp][0];
    float* shB = selfpair ? shA : s_fe[warp][1];
    load_row(shA, fe, fn, S, n1a, n2a, e, lane);
    if (!selfpair) load_row(shB, fe, fn, S, n1a, n2a, ie, lane);
    __syncwarp();

    float* o  = out + (long long)j * D * D;
    float* oT = selfpair ? (float*)nullptr : out + (long long)p * D * D;

    if (T == 0) {
        // slots (L,AM,OFF): (0,0,0), (1,2,1)
        do_block<0,0,0,0, 0,0, 4,4>(lane, s_cg, shA, shB, o, oT);
        do_block<0,1,0,2, 0,1, 4,4>(lane, s_cg, shA, shB, o, oT);
        do_block<1,0,2,0, 1,0, 4,4>(lane, s_cg, shA, shB, o, oT);
        do_block<1,1,2,2, 1,1, 4,4>(lane, s_cg, shA, shB, o, oT);
    } else {
        // slots (L,AM,OFF): (0,0,0), (0,1,1), (1,2,2), (2,3,5)
        do_block<0,0,0,0, 0,0, 10,10>(lane, s_cg, shA, shB, o, oT);
        do_block<0,0,0,1, 0,1, 10,10>(lane, s_cg, shA, shB, o, oT);
        do_block<0,1,0,2, 0,2, 10,10>(lane, s_cg, shA, shB, o, oT);
        do_block<0,2,0,3, 0,5, 10,10>(lane, s_cg, shA, shB, o, oT);
        do_block<0,0,1,0, 1,0, 10,10>(lane, s_cg, shA, shB, o, oT);
        do_block<0,0,1,1, 1,1, 10,10>(lane, s_cg, shA, shB, o, oT);
        do_block<0,1,1,2, 1,2, 10,10>(lane, s_cg, shA, shB, o, oT);
        do_block<0,2,1,3, 1,5, 10,10>(lane, s_cg, shA, shB, o, oT);
        do_block<1,0,2,0, 2,0, 10,10>(lane, s_cg, shA, shB, o, oT);
        do_block<1,0,2,1, 2,1, 10,10>(lane, s_cg, shA, shB, o, oT);
        do_block<1,1,2,2, 2,2, 10,10>(lane, s_cg, shA, shB, o, oT);
        do_block<1,2,2,3, 2,5, 10,10>(lane, s_cg, shA, shB, o, oT);
        do_block<2,0,3,0, 5,0, 10,10>(lane, s_cg, shA, shB, o, oT);
        do_block<2,0,3,1, 5,1, 10,10>(lane, s_cg, shA, shB, o, oT);
        do_block<2,1,3,2, 5,2, 10,10>(lane, s_cg, shA, shB, o, oT);
        do_block<2,2,3,3, 5,5, 10,10>(lane, s_cg, shA, shB, o, oT);
    }
}

// Cross pairs: warp per j in sel01; writes ham01[j] and ham10[p] = transpose.
__global__ void ham_cross(
    const float* __restrict__ fe, const float* __restrict__ fn,
    const float* __restrict__ S,
    const int* __restrict__ n1a, const int* __restrict__ n2a,
    const int* __restrict__ einv,
    const int* __restrict__ sel01, int n01,
    CgPtrs cg, float* __restrict__ out01, float* __restrict__ out10)
{
    __shared__ float s_cg[CG_TOTAL];
    __shared__ float s_fe[8][2][100];
    load_cg_shared(s_cg, cg);
    __syncthreads();

    int warp = threadIdx.x >> 5;
    int lane = threadIdx.x & 31;
    int j = blockIdx.x * 8 + warp;
    if (j >= n01) return;

    int e  = __ldg(sel01 + j);
    int ie = __ldg(einv + e);
    int p  = g2b_scratch[ie];          // index within sel10

    float* shA = s_fe[warp][0];
    float* shB = s_fe[warp][1];
    load_row(shA, fe, fn, S, n1a, n2a, e, lane);
    load_row(shB, fe, fn, S, n1a, n2a, ie, lane);
    __syncwarp();

    float* o  = out01 + (long long)j * 40;
    float* oT = out10 + (long long)p * 40;

    // T1=0 slots: (0,0,0),(1,2,1);  T2=1 slots: (0,0,0),(0,1,1),(1,2,2),(2,3,5)
    do_block<0,0,0,0, 0,0, 4,10>(lane, s_cg, shA, shB, o, oT);
    do_block<0,0,0,1, 0,1, 4,10>(lane, s_cg, shA, shB, o, oT);
    do_block<0,1,0,2, 0,2, 4,10>(lane, s_cg, shA, shB, o, oT);
    do_block<0,2,0,3, 0,5, 4,10>(lane, s_cg, shA, shB, o, oT);
    do_block<1,0,2,0, 1,0, 4,10>(lane, s_cg, shA, shB, o, oT);
    do_block<1,0,2,1, 1,1, 4,10>(lane, s_cg, shA, shB, o, oT);
    do_block<1,1,2,2, 1,2, 4,10>(lane, s_cg, shA, shB, o, oT);
    do_block<1,2,2,3, 1,5, 4,10>(lane, s_cg, shA, shB, o, oT);
}

extern "C" void kernel_launch(void* const* d_in, const int* in_sizes, int n_in,
                              void* d_out, int out_size) {
    const float* fn  = (const float*)d_in[0];   // feature_node  (N,100)
    const float* fe  = (const float*)d_in[1];   // feature_edge  (E,100)
    const float* S   = (const float*)d_in[2];   // S_hop         (E,3)
    const int*  eidx = (const int*)d_in[3];     // edge_index_hop (2,E)
    const int*  einv = (const int*)d_in[5];     // edge_inverse  (E,)
    CgPtrs cg;
    for (int i = 0; i < 9; i++) cg.p[i] = (const float*)d_in[6 + i];
    const int* s00 = (const int*)d_in[15]; int n00 = in_sizes[15];
    const int* s01 = (const int*)d_in[16]; int n01 = in_sizes[16];
    const int* s10 = (const int*)d_in[17]; int n10 = in_sizes[17];
    const int* s11 = (const int*)d_in[18]; int n11 = in_sizes[18];

    int E = in_sizes[1] / 100;
    const int* n1a = eidx;
    const int* n2a = eidx + E;
    float* out = (float*)d_out;

    long long o01 = 16LL * n00;
    long long o10 = o01 + 40LL * n01;
    long long o11 = o10 + 40LL * n10;
    long long og  = o11 + 100LL * n11;

    int tot = n00 + n01 + n10 + n11;
    if (tot) g2b_kernel<<<(tot + 255) / 256, 256>>>(s00, n00, s01, n01, s10, n10, s11, n11, out + og);

    if (n00) ham_same<0><<<(n00 + 7) / 8, 256>>>(fe, fn, S, n1a, n2a, einv, s00, n00, cg, out);
    if (n01) ham_cross <<<(n01 + 7) / 8, 256>>>(fe, fn, S, n1a, n2a, einv, s01, n01, cg, out + o01, out + o10);
    if (n11) ham_same<1><<<(n11 + 7) / 8, 256>>>(fe, fn, S, n1a, n2a, einv, s11, n11, cg, out + o11);

    (void)n_in; (void)out_size; (void)s10; (void)n10;
}

// round 5
// speedup vs baseline: 1.9763x; 1.1249x over previous
#include <cuda_runtime.h>

#define CG_TOTAL 1225
#define PAIRS 8
#define WARPS 4   // 128 threads/block, 32 pairs per block

__constant__ int c_cgoff[9] = {0,1,10,35,44,125,350,375,600};

__host__ __device__ constexpr int PFX(int b) {
    const int t[16] = {0,1,2,5,10,11,12,15,20,23,26,35,50,55,60,75};
    return t[b];
}
__host__ __device__ constexpr int CGO(int p) {
    const int t[9] = {0,1,10,35,44,125,350,375,600};
    return t[p];
}

struct KP {
    const float *fe, *fn, *S;
    const int *n1a, *n2a, *einv;
    const float* cg[9];
    const int *sel00, *sel01, *sel10, *sel11;
    int n00, n01, n10, n11;
    int b1, b2, b3, b4;           // exclusive block-range ends for 00,01,10,11
    float *out00, *out01, *out10, *out11, *outg;
};

__device__ __forceinline__ void load_cg_shared(float* s_cg, const KP& P) {
    for (int t = threadIdx.x; t < CG_TOTAL; t += blockDim.x) {
        int p = 0;
        #pragma unroll
        for (int q = 1; q < 9; q++) if (t >= c_cgoff[q]) p = q;
        s_cg[t] = __ldg(P.cg[p] + (t - c_cgoff[p]));
    }
}

// One (slot1,slot2) block for a warp's 8 pairs.
// Lane l < SZ computes element (li,lj) = (l/W2, l%W2):
//   A = pre_{T1T2}[e]  block (AM1,AM2) elem (li,lj)
//   B = pre_{T2T1}[ie] block (AM2,AM1) elem (lj,li)
//   out[j][(ROFF+li)*D2 + COFF+lj] = 0.5(A+B)
template<int L1,int L2,int AM1,int AM2,int ROFF,int COFF,int D1,int D2>
__device__ __forceinline__ void blk(int lane, int nvalid, int j,
    const float* __restrict__ s_cg,
    const float* __restrict__ s_feA, const float* __restrict__ s_feB,
    float* __restrict__ out)
{
    constexpr int W1 = 2*L1+1, W2 = 2*L2+1, SZ = W1*W2;
    constexpr int offA = PFX(4*AM1+AM2), offB = PFX(4*AM2+AM1);
    constexpr int A0 = offA & ~3, B0 = offB & ~3;
    constexpr int SA = offA - A0, SB = offB - B0;
    constexpr int NA = (SA + SZ + 3) / 4, NB = (SB + SZ + 3) / 4;

    int li = lane / W2, lj = lane % W2;
    float cgA[SZ], cgB[SZ];
    if (lane < SZ) {
        const float* ca = s_cg + CGO(L1*3+L2) + lane * SZ;
        const float* cb = s_cg + CGO(L2*3+L1) + (lj*W1+li) * SZ;
        #pragma unroll
        for (int k = 0; k < SZ; k++) cgA[k] = ca[k];
        #pragma unroll
        for (int k = 0; k < SZ; k++) cgB[k] = cb[k];
    }

    #pragma unroll 2
    for (int pr = 0; pr < PAIRS; pr++) {
        if (pr >= nvalid) break;
        const float4* pa = (const float4*)(s_feA + pr*100 + A0);
        const float4* pb = (const float4*)(s_feB + pr*100 + B0);
        float A = 0.f, B = 0.f;
        #pragma unroll
        for (int v = 0; v < NA; v++) {
            float4 t = pa[v];
            int k0 = 4*v - SA;
            if (k0+0 >= 0 && k0+0 < SZ) A += t.x * cgA[(k0+0 >= 0 && k0+0 < SZ) ? k0+0 : 0];
            if (k0+1 >= 0 && k0+1 < SZ) A += t.y * cgA[(k0+1 >= 0 && k0+1 < SZ) ? k0+1 : 0];
            if (k0+2 >= 0 && k0+2 < SZ) A += t.z * cgA[(k0+2 >= 0 && k0+2 < SZ) ? k0+2 : 0];
            if (k0+3 >= 0 && k0+3 < SZ) A += t.w * cgA[(k0+3 >= 0 && k0+3 < SZ) ? k0+3 : 0];
        }
        #pragma unroll
        for (int v = 0; v < NB; v++) {
            float4 t = pb[v];
            int k0 = 4*v - SB;
            if (k0+0 >= 0 && k0+0 < SZ) B += t.x * cgB[(k0+0 >= 0 && k0+0 < SZ) ? k0+0 : 0];
            if (k0+1 >= 0 && k0+1 < SZ) B += t.y * cgB[(k0+1 >= 0 && k0+1 < SZ) ? k0+1 : 0];
            if (k0+2 >= 0 && k0+2 < SZ) B += t.z * cgB[(k0+2 >= 0 && k0+2 < SZ) ? k0+2 : 0];
            if (k0+3 >= 0 && k0+3 < SZ) B += t.w * cgB[(k0+3 >= 0 && k0+3 < SZ) ? k0+3 : 0];
        }
        int jp = __shfl_sync(0xffffffffu, j, pr);
        if (lane < SZ)
            out[(size_t)jp * (D1*D2) + (ROFF+li)*D2 + (COFF+lj)] = 0.5f * (A + B);
    }
}

#define BLK(L1,L2,AM1,AM2,RO,CO,D1,D2) \
    blk<L1,L2,AM1,AM2,RO,CO,D1,D2>(lane, nvalid, j, s_cg, s_feA, s_feB, out)

template<int T1,int T2>
__device__ __forceinline__ void ham_list(int rel, const KP& P,
    const int* __restrict__ sel, int n, float* __restrict__ out,
    const float* s_cg, float* s_fe)
{
    int warp = threadIdx.x >> 5, lane = threadIdx.x & 31;
    float* s_feA = s_fe + warp * (2 * PAIRS * 100);
    float* s_feB = s_feA + PAIRS * 100;
    int base = (rel * WARPS + warp) * PAIRS;
    if (base >= n) return;
    int nvalid = min(PAIRS, n - base);

    int j = 0, e = 0, ie = 0;
    if (lane < nvalid) {
        j  = base + lane;
        e  = __ldg(sel + j);
        ie = __ldg(P.einv + e);
    }

    // Stage fe rows (with self-edge node-feature add) for both sides of 8 pairs.
    for (int r = 0; r < 2 * nvalid; r++) {
        int pr = r >> 1;
        int eA = __shfl_sync(0xffffffffu, e,  pr);
        int eB = __shfl_sync(0xffffffffu, ie, pr);
        int edge = (r & 1) ? eB : eA;
        float* dst = ((r & 1) ? s_feB : s_feA) + pr * 100;
        int a  = __ldg(P.n1a + edge);
        int bb = __ldg(P.n2a + edge);
        bool self = false;
        if (a == bb) {
            float sx = __ldg(P.S + 3*edge), sy = __ldg(P.S + 3*edge + 1), sz = __ldg(P.S + 3*edge + 2);
            self = (sx*sx + sy*sy + sz*sz) < 1e-12f;
        }
        if (lane < 25) {
            float4 v = __ldg((const float4*)(P.fe + (size_t)edge * 100) + lane);
            if (self) {
                float4 w = __ldg((const float4*)(P.fn + (size_t)a * 100) + lane);
                v.x += w.x; v.y += w.y; v.z += w.z; v.w += w.w;
            }
            ((float4*)dst)[lane] = v;
        }
    }
    __syncwarp();

    // Type slot tables: type0 slots (L,AM,OFF): (0,0,0),(1,2,1)
    //                   type1 slots:            (0,0,0),(0,1,1),(1,2,2),(2,3,5)
    if constexpr (T1 == 0 && T2 == 0) {
        BLK(0,0,0,0, 0,0, 4,4);  BLK(0,1,0,2, 0,1, 4,4);
        BLK(1,0,2,0, 1,0, 4,4);  BLK(1,1,2,2, 1,1, 4,4);
    } else if constexpr (T1 == 0 && T2 == 1) {
        BLK(0,0,0,0, 0,0, 4,10); BLK(0,0,0,1, 0,1, 4,10);
        BLK(0,1,0,2, 0,2, 4,10); BLK(0,2,0,3, 0,5, 4,10);
        BLK(1,0,2,0, 1,0, 4,10); BLK(1,0,2,1, 1,1, 4,10);
        BLK(1,1,2,2, 1,2, 4,10); BLK(1,2,2,3, 1,5, 4,10);
    } else if constexpr (T1 == 1 && T2 == 0) {
        BLK(0,0,0,0, 0,0, 10,4); BLK(0,1,0,2, 0,1, 10,4);
        BLK(0,0,1,0, 1,0, 10,4); BLK(0,1,1,2, 1,1, 10,4);
        BLK(1,0,2,0, 2,0, 10,4); BLK(1,1,2,2, 2,1, 10,4);
        BLK(2,0,3,0, 5,0, 10,4); BLK(2,1,3,2, 5,1, 10,4);
    } else {
        BLK(0,0,0,0, 0,0, 10,10); BLK(0,0,0,1, 0,1, 10,10);
        BLK(0,1,0,2, 0,2, 10,10); BLK(0,2,0,3, 0,5, 10,10);
        BLK(0,0,1,0, 1,0, 10,10); BLK(0,0,1,1, 1,1, 10,10);
        BLK(0,1,1,2, 1,2, 10,10); BLK(0,2,1,3, 1,5, 10,10);
        BLK(1,0,2,0, 2,0, 10,10); BLK(1,0,2,1, 2,1, 10,10);
        BLK(1,1,2,2, 2,2, 10,10); BLK(1,2,2,3, 2,5, 10,10);
        BLK(2,0,3,0, 5,0, 10,10); BLK(2,0,3,1, 5,1, 10,10);
        BLK(2,1,3,2, 5,2, 10,10); BLK(2,2,3,3, 5,5, 10,10);
    }
}

__global__ __launch_bounds__(128) void fused_kernel(KP P) {
    int b = blockIdx.x;

    if (b >= P.b4) {
        // g2b tail: outg[sel_p[i]] = i
        int t = (b - P.b4) * 128 + threadIdx.x;
        int tot = P.n00 + P.n01 + P.n10 + P.n11;
        if (t < tot) {
            const int* s; int loc;
            if (t < P.n00)                         { s = P.sel00; loc = t; }
            else if (t < P.n00 + P.n01)            { s = P.sel01; loc = t - P.n00; }
            else if (t < P.n00 + P.n01 + P.n10)    { s = P.sel10; loc = t - P.n00 - P.n01; }
            else                                   { s = P.sel11; loc = t - P.n00 - P.n01 - P.n10; }
            P.outg[__ldg(s + loc)] = (float)loc;
        }
        return;
    }

    __shared__ __align__(16) float s_cg[(CG_TOTAL + 3) & ~3];
    __shared__ __align__(16) float s_fe[WARPS * 2 * PAIRS * 100];
    load_cg_shared(s_cg, P);
    __syncthreads();

    if (b < P.b1)       ham_list<0,0>(b,        P, P.sel00, P.n00, P.out00, s_cg, s_fe);
    else if (b < P.b2)  ham_list<0,1>(b - P.b1, P, P.sel01, P.n01, P.out01, s_cg, s_fe);
    else if (b < P.b3)  ham_list<1,0>(b - P.b2, P, P.sel10, P.n10, P.out10, s_cg, s_fe);
    else                ham_list<1,1>(b - P.b3, P, P.sel11, P.n11, P.out11, s_cg, s_fe);
}

extern "C" void kernel_launch(void* const* d_in, const int* in_sizes, int n_in,
                              void* d_out, int out_size) {
    KP P;
    P.fe   = (const float*)d_in[1];
    P.fn   = (const float*)d_in[0];
    P.S    = (const float*)d_in[2];
    const int* eidx = (const int*)d_in[3];
    P.einv = (const int*)d_in[5];
    for (int i = 0; i < 9; i++) P.cg[i] = (const float*)d_in[6 + i];
    P.sel00 = (const int*)d_in[15]; P.n00 = in_sizes[15];
    P.sel01 = (const int*)d_in[16]; P.n01 = in_sizes[16];
    P.sel10 = (const int*)d_in[17]; P.n10 = in_sizes[17];
    P.sel11 = (const int*)d_in[18]; P.n11 = in_sizes[18];

    int E = in_sizes[1] / 100;
    P.n1a = eidx;
    P.n2a = eidx + E;

    float* out = (float*)d_out;
    P.out00 = out;
    P.out01 = P.out00 + 16LL  * P.n00;
    P.out10 = P.out01 + 40LL  * P.n01;
    P.out11 = P.out10 + 40LL  * P.n10;
    P.outg  = P.out11 + 100LL * P.n11;

    const int ppb = WARPS * PAIRS;  // 32 pairs per block
    int nb00 = (P.n00 + ppb - 1) / ppb;
    int nb01 = (P.n01 + ppb - 1) / ppb;
    int nb10 = (P.n10 + ppb - 1) / ppb;
    int nb11 = (P.n11 + ppb - 1) / ppb;
    P.b1 = nb00;
    P.b2 = P.b1 + nb01;
    P.b3 = P.b2 + nb10;
    P.b4 = P.b3 + nb11;
    int tot = P.n00 + P.n01 + P.n10 + P.n11;
    int nbg = (tot + 127) / 128;

    int grid = P.b4 + nbg;
    if (grid > 0) fused_kernel<<<grid, 128>>>(P);

    (void)n_in; (void)out_size;
}

// round 7
// speedup vs baseline: 2.5828x; 1.3069x over previous
#include <cuda_runtime.h>

#define CG_TOTAL 1225
#define PAIRS 8
#define WARPS 4   // 128 threads/block, 32 candidate pairs per block
#define FULLM 0xffffffffu

__constant__ int c_cgoff[9] = {0,1,10,35,44,125,350,375,600};

__host__ __device__ constexpr int PFX(int b) {
    const int t[16] = {0,1,2,5,10,11,12,15,20,23,26,35,50,55,60,75};
    return t[b];
}
__host__ __device__ constexpr int CGO(int p) {
    const int t[9] = {0,1,10,35,44,125,350,375,600};
    return t[p];
}

// Local index of each edge within its type-pair sel list.
__device__ int g2b_scratch[524288];

struct KP {
    const float *fe, *fn, *S;
    const int *n1a, *n2a, *einv;
    const float* cg[9];
    const int *sel00, *sel01, *sel11;
    int n00, n01, n11;
    int b1, b2, b3;               // exclusive block-range ends for 00,01,11
    float *out00, *out01, *out10, *out11;
};

__global__ void g2b_kernel(const int* __restrict__ s00, int n00,
                           const int* __restrict__ s01, int n01,
                           const int* __restrict__ s10, int n10,
                           const int* __restrict__ s11, int n11,
                           float* __restrict__ outg)
{
    int total = n00 + n01 + n10 + n11;
    for (int t = blockIdx.x * blockDim.x + threadIdx.x; t < total;
         t += gridDim.x * blockDim.x) {
        const int* s; int loc;
        if (t < n00)                  { s = s00; loc = t; }
        else if (t < n00 + n01)       { s = s01; loc = t - n00; }
        else if (t < n00 + n01 + n10) { s = s10; loc = t - n00 - n01; }
        else                          { s = s11; loc = t - n00 - n01 - n10; }
        int e = __ldg(s + loc);
        g2b_scratch[e] = loc;
        outg[e] = (float)loc;
    }
}

__device__ __forceinline__ void load_cg_shared(float* s_cg, const KP& P) {
    for (int t = threadIdx.x; t < CG_TOTAL; t += blockDim.x) {
        int p = 0;
        #pragma unroll
        for (int q = 1; q < 9; q++) if (t >= c_cgoff[q]) p = q;
        s_cg[t] = __ldg(P.cg[p] + (t - c_cgoff[p]));
    }
}

// One (slot1,slot2) block for a warp's nv compacted pairs.
// Lane l < SZ computes element (li,lj) = (l/W2, l%W2):
//   A = pre_{T1T2}[e]  block (AM1,AM2) elem (li,lj)
//   B = pre_{T2T1}[ie] block (AM2,AM1) elem (lj,li)
//   M = 0.5(A+B)
//   out [j][(ROFF+li)*D2 + COFF+lj] = M
//   outT[p][(COFF+lj)*D1 + ROFF+li] = M      (outT row is D2 x D1)
template<int L1,int L2,int AM1,int AM2,int ROFF,int COFF,int D1,int D2>
__device__ __forceinline__ void blk(int lane, int nv, int j, int p,
    const float* __restrict__ s_cg,
    const float* __restrict__ s_feA, const float* __restrict__ s_feB,
    float* __restrict__ out, float* __restrict__ outT)
{
    constexpr int W1 = 2*L1+1, W2 = 2*L2+1, SZ = W1*W2;
    constexpr int offA = PFX(4*AM1+AM2), offB = PFX(4*AM2+AM1);
    constexpr int A0 = offA & ~3, B0 = offB & ~3;
    constexpr int SA = offA - A0, SB = offB - B0;
    constexpr int NA = (SA + SZ + 3) / 4, NB = (SB + SZ + 3) / 4;

    int li = lane / W2, lj = lane % W2;
    float cgA[SZ], cgB[SZ];
    if (lane < SZ) {
        const float* ca = s_cg + CGO(L1*3+L2) + lane * SZ;
        const float* cb = s_cg + CGO(L2*3+L1) + (lj*W1+li) * SZ;
        #pragma unroll
        for (int k = 0; k < SZ; k++) cgA[k] = ca[k];
        #pragma unroll
        for (int k = 0; k < SZ; k++) cgB[k] = cb[k];
    }

    #pragma unroll 2
    for (int pr = 0; pr < nv; pr++) {
        const float4* pa = (const float4*)(s_feA + pr*100 + A0);
        const float4* pb = (const float4*)(s_feB + pr*100 + B0);
        float A = 0.f, B = 0.f;
        #pragma unroll
        for (int v = 0; v < NA; v++) {
            float4 t = pa[v];
            int k0 = 4*v - SA;
            if (k0+0 >= 0 && k0+0 < SZ) A += t.x * cgA[(k0+0 >= 0 && k0+0 < SZ) ? k0+0 : 0];
            if (k0+1 >= 0 && k0+1 < SZ) A += t.y * cgA[(k0+1 >= 0 && k0+1 < SZ) ? k0+1 : 0];
            if (k0+2 >= 0 && k0+2 < SZ) A += t.z * cgA[(k0+2 >= 0 && k0+2 < SZ) ? k0+2 : 0];
            if (k0+3 >= 0 && k0+3 < SZ) A += t.w * cgA[(k0+3 >= 0 && k0+3 < SZ) ? k0+3 : 0];
        }
        #pragma unroll
        for (int v = 0; v < NB; v++) {
            float4 t = pb[v];
            int k0 = 4*v - SB;
            if (k0+0 >= 0 && k0+0 < SZ) B += t.x * cgB[(k0+0 >= 0 && k0+0 < SZ) ? k0+0 : 0];
            if (k0+1 >= 0 && k0+1 < SZ) B += t.y * cgB[(k0+1 >= 0 && k0+1 < SZ) ? k0+1 : 0];
            if (k0+2 >= 0 && k0+2 < SZ) B += t.z * cgB[(k0+2 >= 0 && k0+2 < SZ) ? k0+2 : 0];
            if (k0+3 >= 0 && k0+3 < SZ) B += t.w * cgB[(k0+3 >= 0 && k0+3 < SZ) ? k0+3 : 0];
        }
        int jp = __shfl_sync(FULLM, j, pr);
        int pp = __shfl_sync(FULLM, p, pr);
        if (lane < SZ) {
            float M = 0.5f * (A + B);
            out [(size_t)jp * (D1*D2) + (ROFF+li)*D2 + (COFF+lj)] = M;
            outT[(size_t)pp * (D1*D2) + (COFF+lj)*D1 + (ROFF+li)] = M;
        }
    }
}

#define BLK(L1,L2,AM1,AM2,RO,CO,D1,D2) \
    blk<L1,L2,AM1,AM2,RO,CO,D1,D2>(lane, nv, j, p, s_cg, s_feA, s_feB, out, outT)

// SAME=true: canonical filter p>=j, outT==out. SAME=false: 01 list, outT=out10.
template<int T1,int T2>
__device__ __forceinline__ void ham_list(int rel, const KP& P,
    const int* __restrict__ sel, int n,
    float* __restrict__ out, float* __restrict__ outT,
    const float* s_cg, float* s_fe)
{
    constexpr bool SAME = (T1 == T2);
    int warp = threadIdx.x >> 5, lane = threadIdx.x & 31;
    float* s_feA = s_fe + warp * (2 * PAIRS * 100);
    float* s_feB = s_feA + PAIRS * 100;
    int base = (rel * WARPS + warp) * PAIRS;
    if (base >= n) return;
    int navail = min(PAIRS, n - base);

    int j = 0, e = 0, ie = 0, p = 0;
    bool v = false;
    if (lane < navail) {
        j  = base + lane;
        e  = __ldg(sel + j);
        ie = __ldg(P.einv + e);
        p  = g2b_scratch[ie];
        v  = SAME ? (p >= j) : true;
    }
    unsigned m = __ballot_sync(FULLM, v);
    int nv = __popc(m);
    if (nv == 0) return;

    // Compact valid pairs to lanes 0..nv-1.
    int sl = (lane < nv) ? __fns(m, 0, lane + 1) : 0;
    j  = __shfl_sync(FULLM, j,  sl);
    e  = __shfl_sync(FULLM, e,  sl);
    ie = __shfl_sync(FULLM, ie, sl);
    p  = __shfl_sync(FULLM, p,  sl);

    // Stage fe rows (with self-edge node-feature add) for both sides.
    for (int r = 0; r < 2 * nv; r++) {
        int pr = r >> 1;
        int eA = __shfl_sync(FULLM, e,  pr);
        int eB = __shfl_sync(FULLM, ie, pr);
        int edge = (r & 1) ? eB : eA;
        float* dst = ((r & 1) ? s_feB : s_feA) + pr * 100;
        int a  = __ldg(P.n1a + edge);
        int bb = __ldg(P.n2a + edge);
        bool self = false;
        if (a == bb) {
            float sx = __ldg(P.S + 3*edge), sy = __ldg(P.S + 3*edge + 1), sz = __ldg(P.S + 3*edge + 2);
            self = (sx*sx + sy*sy + sz*sz) < 1e-12f;
        }
        if (lane < 25) {
            float4 vv = __ldg((const float4*)(P.fe + (size_t)edge * 100) + lane);
            if (self) {
                float4 w = __ldg((const float4*)(P.fn + (size_t)a * 100) + lane);
                vv.x += w.x; vv.y += w.y; vv.z += w.z; vv.w += w.w;
            }
            ((float4*)dst)[lane] = vv;
        }
    }
    __syncwarp();

    // Type slot tables: type0 slots (L,AM,OFF): (0,0,0),(1,2,1)
    //                   type1 slots:            (0,0,0),(0,1,1),(1,2,2),(2,3,5)
    if constexpr (T1 == 0 && T2 == 0) {
        BLK(0,0,0,0, 0,0, 4,4);  BLK(0,1,0,2, 0,1, 4,4);
        BLK(1,0,2,0, 1,0, 4,4);  BLK(1,1,2,2, 1,1, 4,4);
    } else if constexpr (T1 == 0 && T2 == 1) {
        BLK(0,0,0,0, 0,0, 4,10); BLK(0,0,0,1, 0,1, 4,10);
        BLK(0,1,0,2, 0,2, 4,10); BLK(0,2,0,3, 0,5, 4,10);
        BLK(1,0,2,0, 1,0, 4,10); BLK(1,0,2,1, 1,1, 4,10);
        BLK(1,1,2,2, 1,2, 4,10); BLK(1,2,2,3, 1,5, 4,10);
    } else {
        BLK(0,0,0,0, 0,0, 10,10); BLK(0,0,0,1, 0,1, 10,10);
        BLK(0,1,0,2, 0,2, 10,10); BLK(0,2,0,3, 0,5, 10,10);
        BLK(0,0,1,0, 1,0, 10,10); BLK(0,0,1,1, 1,1, 10,10);
        BLK(0,1,1,2, 1,2, 10,10); BLK(0,2,1,3, 1,5, 10,10);
        BLK(1,0,2,0, 2,0, 10,10); BLK(1,0,2,1, 2,1, 10,10);
        BLK(1,1,2,2, 2,2, 10,10); BLK(1,2,2,3, 2,5, 10,10);
        BLK(2,0,3,0, 5,0, 10,10); BLK(2,0,3,1, 5,1, 10,10);
        BLK(2,1,3,2, 5,2, 10,10); BLK(2,2,3,3, 5,5, 10,10);
    }
}

__global__ __launch_bounds__(128) void fused_kernel(KP P) {
    __shared__ __align__(16) float s_cg[(CG_TOTAL + 3) & ~3];
    __shared__ __align__(16) float s_fe[WARPS * 2 * PAIRS * 100];
    load_cg_shared(s_cg, P);
    __syncthreads();

    int b = blockIdx.x;
    if (b < P.b1)       ham_list<0,0>(b,        P, P.sel00, P.n00, P.out00, P.out00, s_cg, s_fe);
    else if (b < P.b2)  ham_list<0,1>(b - P.b1, P, P.sel01, P.n01, P.out01, P.out10, s_cg, s_fe);
    else                ham_list<1,1>(b - P.b2, P, P.sel11, P.n11, P.out11, P.out11, s_cg, s_fe);
}

extern "C" void kernel_launch(void* const* d_in, const int* in_sizes, int n_in,
                              void* d_out, int out_size) {
    KP P;
    P.fn   = (const float*)d_in[0];
    P.fe   = (const float*)d_in[1];
    P.S    = (const float*)d_in[2];
    const int* eidx = (const int*)d_in[3];
    P.einv = (const int*)d_in[5];
    for (int i = 0; i < 9; i++) P.cg[i] = (const float*)d_in[6 + i];
    P.sel00 = (const int*)d_in[15]; P.n00 = in_sizes[15];
    P.sel01 = (const int*)d_in[16]; P.n01 = in_sizes[16];
    const int* sel10 = (const int*)d_in[17]; int n10 = in_sizes[17];
    P.sel11 = (const int*)d_in[18]; P.n11 = in_sizes[18];

    int E = in_sizes[1] / 100;
    P.n1a = eidx;
    P.n2a = eidx + E;

    float* out = (float*)d_out;
    P.out00 = out;
    P.out01 = P.out00 + 16LL  * P.n00;
    P.out10 = P.out01 + 40LL  * P.n01;
    P.out11 = P.out10 + 40LL  * n10;
    float* outg = P.out11 + 100LL * P.n11;

    const int ppb = WARPS * PAIRS;  // 32 candidate pairs per block
    int nb00 = (P.n00 + ppb - 1) / ppb;
    int nb01 = (P.n01 + ppb - 1) / ppb;
    int nb11 = (P.n11 + ppb - 1) / ppb;
    P.b1 = nb00;
    P.b2 = P.b1 + nb01;
    P.b3 = P.b2 + nb11;

    int tot = P.n00 + P.n01 + n10 + P.n11;
    if (tot) g2b_kernel<<<(tot + 255) / 256, 256>>>(P.sel00, P.n00, P.sel01, P.n01,
                                                    sel10, n10, P.sel11, P.n11, outg);
    if (P.b3 > 0) fused_kernel<<<P.b3, 128>>>(P);

    (void)n_in; (void)out_size;
}